// round 2
// baseline (speedup 1.0000x reference)
#include <cuda_runtime.h>
#include <math.h>

// YOLO loss reduction. n cells (802816), each:
//   pred: 30 f32 (2 boxes x 5 + 20 class scores)
//   tbox: 4 f32, tcls: 20 f32, mask: 1 elem (dtype detected at runtime)
// Outputs 5 f32: total, reg, containing, noobj, cls

#define S_GRID_INV (1.0f / 14.0f)
#define L_COORD 5.0f
#define L_NOOBJ 0.5f

__device__ double g_acc[4];     // cls, noobj(raw conf^2), reg(raw), containing
__device__ int g_mask_mode;     // 0=int32, 1=uint8, 2=float32

__global__ void detect_mask_kernel(const unsigned int* __restrict__ m, int nwords) {
    __shared__ int gt1, badbyte;
    if (threadIdx.x == 0) { gt1 = 0; badbyte = 0; g_acc[0]=0.0; g_acc[1]=0.0; g_acc[2]=0.0; g_acc[3]=0.0; }
    __syncthreads();
    int local_gt1 = 0, local_bad = 0;
    for (int i = threadIdx.x; i < nwords; i += blockDim.x) {
        unsigned w = m[i];
        if (w > 1u) local_gt1 = 1;
        unsigned b0 = w & 0xFFu, b1 = (w >> 8) & 0xFFu,
                 b2 = (w >> 16) & 0xFFu, b3 = w >> 24;
        if (b0 > 1u || b1 > 1u || b2 > 1u || b3 > 1u) local_bad = 1;
    }
    if (local_gt1) atomicOr(&gt1, 1);
    if (local_bad) atomicOr(&badbyte, 1);
    __syncthreads();
    if (threadIdx.x == 0) {
        g_mask_mode = (gt1 == 0) ? 0 : (badbyte ? 2 : 1);
    }
}

__global__ void __launch_bounds__(256) yolo_main_kernel(
    const float* __restrict__ pred,
    const float* __restrict__ tbox,
    const float* __restrict__ tcls,
    const void* __restrict__ maskv,
    int ncell)
{
    const int mode = g_mask_mode;
    const int* mask_i = (const int*)maskv;
    const unsigned char* mask_b = (const unsigned char*)maskv;
    const float* mask_f = (const float*)maskv;

    float s_cls = 0.f, s_noobj = 0.f, s_reg = 0.f, s_cont = 0.f;

    for (int c = blockIdx.x * blockDim.x + threadIdx.x; c < ncell;
         c += gridDim.x * blockDim.x) {

        bool m;
        if (mode == 0)      m = mask_i[c] != 0;
        else if (mode == 1) m = mask_b[c] != 0;
        else                m = mask_f[c] != 0.0f;

        const float* p = pred + (size_t)c * 30;

        if (!m) {
            // only the two confidences matter
            float c0 = __ldg(p + 4);
            float c1 = __ldg(p + 9);
            s_noobj += c0 * c0 + c1 * c1;
            continue;
        }

        // full 30-float cell, 8B-aligned (cell stride 120B), load via float2
        float pv[30];
        const float2* p2 = (const float2*)p;
#pragma unroll
        for (int j = 0; j < 15; j++) {
            float2 v = p2[j];
            pv[2 * j]     = v.x;
            pv[2 * j + 1] = v.y;
        }

        // ---- class loss ----
        {
            const float4* tc4 = (const float4*)(tcls + (size_t)c * 20);
            float cls = 0.f;
#pragma unroll
            for (int j = 0; j < 5; j++) {
                float4 t = tc4[j];
                float d0 = t.x - pv[10 + 4 * j + 0];
                float d1 = t.y - pv[10 + 4 * j + 1];
                float d2 = t.z - pv[10 + 4 * j + 2];
                float d3 = t.w - pv[10 + 4 * j + 3];
                cls += d0 * d0 + d1 * d1 + d2 * d2 + d3 * d3;
            }
            s_cls += cls;
        }

        // ---- IoU for the two pred boxes vs target ----
        float4 tb = ((const float4*)tbox)[c];
        float t_cx = tb.x * S_GRID_INV;
        float t_cy = tb.y * S_GRID_INV;
        float t_x1 = t_cx - 0.5f * tb.z;
        float t_y1 = t_cy - 0.5f * tb.w;
        float t_x2 = t_cx + 0.5f * tb.z;
        float t_y2 = t_cy + 0.5f * tb.w;
        float area_t = (t_x2 - t_x1) * (t_y2 - t_y1);

        float iou[2];
#pragma unroll
        for (int b = 0; b < 2; b++) {
            float px = pv[5 * b + 0] * S_GRID_INV;
            float py = pv[5 * b + 1] * S_GRID_INV;
            float pw = pv[5 * b + 2];
            float ph = pv[5 * b + 3];
            float p_x1 = px - 0.5f * pw;
            float p_y1 = py - 0.5f * ph;
            float p_x2 = px + 0.5f * pw;
            float p_y2 = py + 0.5f * ph;
            float lt_x = fmaxf(t_x1, p_x1);
            float lt_y = fmaxf(t_y1, p_y1);
            float rb_x = fminf(t_x2, p_x2);
            float rb_y = fminf(t_y2, p_y2);
            float w = fmaxf(rb_x - lt_x, 0.0f);
            float h = fmaxf(rb_y - lt_y, 0.0f);
            float inter = w * h;
            float area_p = (p_x2 - p_x1) * (p_y2 - p_y1);
            iou[b] = inter / (area_t + area_p - inter);
        }

        // argmax (jnp.argmax: first max wins; pick 1 only if strictly greater)
        bool sel = iou[1] > iou[0];
        float best_iou = sel ? iou[1] : iou[0];
        float bb_x = sel ? pv[5] : pv[0];
        float bb_y = sel ? pv[6] : pv[1];
        float bb_w = sel ? pv[7] : pv[2];
        float bb_h = sel ? pv[8] : pv[3];
        float bb_c = sel ? pv[9] : pv[4];

        // ---- regression loss (raw, x L_COORD at finalize) ----
        float dx = bb_x - tb.x;
        float dy = bb_y - tb.y;
        float sw = sqrtf(bb_w) - sqrtf(tb.z);
        float sh = sqrtf(bb_h) - sqrtf(tb.w);
        s_reg += dx * dx + dy * dy + sw * sw + sh * sh;

        // ---- containing-object loss ----
        float dc = best_iou - bb_c;
        s_cont += dc * dc;
    }

    // warp reduce
#pragma unroll
    for (int off = 16; off; off >>= 1) {
        s_cls   += __shfl_down_sync(0xFFFFFFFFu, s_cls,   off);
        s_noobj += __shfl_down_sync(0xFFFFFFFFu, s_noobj, off);
        s_reg   += __shfl_down_sync(0xFFFFFFFFu, s_reg,   off);
        s_cont  += __shfl_down_sync(0xFFFFFFFFu, s_cont,  off);
    }

    __shared__ float sm[4][8];
    int wid = threadIdx.x >> 5;
    int lid = threadIdx.x & 31;
    if (lid == 0) {
        sm[0][wid] = s_cls;
        sm[1][wid] = s_noobj;
        sm[2][wid] = s_reg;
        sm[3][wid] = s_cont;
    }
    __syncthreads();
    if (threadIdx.x == 0) {
        float a0 = 0.f, a1 = 0.f, a2 = 0.f, a3 = 0.f;
#pragma unroll
        for (int w = 0; w < 8; w++) {
            a0 += sm[0][w];
            a1 += sm[1][w];
            a2 += sm[2][w];
            a3 += sm[3][w];
        }
        atomicAdd(&g_acc[0], (double)a0);
        atomicAdd(&g_acc[1], (double)a1);
        atomicAdd(&g_acc[2], (double)a2);
        atomicAdd(&g_acc[3], (double)a3);
    }
}

__global__ void finalize_kernel(float* out, int n_batch) {
    double cls   = g_acc[0];
    double noobj = (double)L_NOOBJ * g_acc[1];
    double reg   = (double)L_COORD * g_acc[2];
    double cont  = g_acc[3];
    double total = (cls + noobj + reg + cont) / (double)n_batch;
    out[0] = (float)total;
    out[1] = (float)reg;
    out[2] = (float)cont;
    out[3] = (float)noobj;
    out[4] = (float)cls;
}

extern "C" void kernel_launch(void* const* d_in, const int* in_sizes, int n_in,
                              void* d_out, int out_size) {
    // Identify inputs by element count (robust against ordering):
    // pred = 30n, tcls = 20n, tbox = 4n, mask = n
    const void* ptrs[4] = {d_in[0], d_in[1], d_in[2], d_in[3]};
    long long sz[4] = {in_sizes[0], in_sizes[1], in_sizes[2], in_sizes[3]};

    // smallest = mask
    int im = 0;
    for (int i = 1; i < 4; i++) if (sz[i] < sz[im]) im = i;
    long long n = sz[im];

    const float* pred = nullptr;
    const float* tbox = nullptr;
    const float* tcls = nullptr;
    const void*  hmask = ptrs[im];
    for (int i = 0; i < 4; i++) {
        if (i == im) continue;
        if (sz[i] == 30 * n) pred = (const float*)ptrs[i];
        else if (sz[i] == 20 * n) tcls = (const float*)ptrs[i];
        else if (sz[i] == 4 * n) tbox = (const float*)ptrs[i];
    }

    int ncell = (int)n;                 // 4096*14*14 = 802816
    int n_batch = ncell / (14 * 14);    // 4096

    // Detect mask dtype from a 4K-word sample (also zeroes accumulators).
    int sample_words = 4096;
    if (sample_words > ncell / 4) sample_words = ncell / 4;  // safe for any dtype
    detect_mask_kernel<<<1, 256>>>((const unsigned int*)hmask, sample_words);

    int threads = 256;
    int blocks = (ncell + threads - 1) / threads;  // 3136
    yolo_main_kernel<<<blocks, threads>>>(pred, tbox, tcls, hmask, ncell);
    finalize_kernel<<<1, 1>>>((float*)d_out, n_batch);
}

// round 3
// speedup vs baseline: 1.0170x; 1.0170x over previous
#include <cuda_runtime.h>
#include <math.h>

// YOLO loss reduction. n cells (802816), each:
//   pred: 30 f32 (2 boxes x 5 + 20 class scores)
//   tbox: 4 f32, tcls: 20 f32, mask: 1 elem (dtype detected inline)
// Outputs 5 f32: total, reg, containing, noobj, cls

#define S_GRID_INV (1.0f / 14.0f)
#define L_COORD 5.0f
#define L_NOOBJ 0.5f
#define TPB 256

__device__ double g_acc[4];  // cls, noobj(raw), reg(raw), containing

__global__ void init_acc_kernel() {
    if (threadIdx.x < 4) g_acc[threadIdx.x] = 0.0;
}

__global__ void __launch_bounds__(TPB) yolo_main_kernel(
    const float* __restrict__ pred,
    const float* __restrict__ tbox,
    const float* __restrict__ tcls,
    const void* __restrict__ maskv,
    int ncell)
{
    __shared__ float sp[TPB * 30];   // pred tile  (30 KB)
    __shared__ float st[TPB * 20];   // tcls tile  (20 KB)
    __shared__ int s_gt1, s_bad;

    const int tid = threadIdx.x;
    const int block0 = blockIdx.x * TPB;

    if (tid == 0) { s_gt1 = 0; s_bad = 0; }
    __syncthreads();

    // ---- inline mask dtype detection (first 256 words; deterministic) ----
    {
        unsigned w = ((const unsigned*)maskv)[tid];
        bool gt1 = w > 1u;
        bool bad = ((w & 0xFFu) > 1u) | (((w >> 8) & 0xFFu) > 1u) |
                   (((w >> 16) & 0xFFu) > 1u) | ((w >> 24) > 1u);
        unsigned bg = __ballot_sync(0xFFFFFFFFu, gt1);
        unsigned bb = __ballot_sync(0xFFFFFFFFu, bad);
        if ((tid & 31) == 0) {
            if (bg) atomicOr(&s_gt1, 1);
            if (bb) atomicOr(&s_bad, 1);
        }
    }

    // ---- coalesced staging into smem ----
    {
        // pred tile: 256 cells * 30 floats = 3840 float2
        const float2* gp2 = (const float2*)(pred + (size_t)block0 * 30);
        float2* sp2 = (float2*)sp;
        long long lim_p = ((long long)ncell * 30 - (long long)block0 * 30) / 2;
#pragma unroll
        for (int k = 0; k < 15; k++) {
            int i = tid + k * TPB;
            if (i < lim_p) sp2[i] = gp2[i];
        }
        // tcls tile: 256 cells * 20 floats = 1280 float4
        const float4* gt4 = (const float4*)(tcls + (size_t)block0 * 20);
        float4* st4 = (float4*)st;
        long long lim_t = ((long long)ncell * 20 - (long long)block0 * 20) / 4;
#pragma unroll
        for (int k = 0; k < 5; k++) {
            int i = tid + k * TPB;
            if (i < lim_t) st4[i] = gt4[i];
        }
    }
    __syncthreads();

    const int mode = (s_gt1 == 0) ? 0 : (s_bad ? 2 : 1);

    float s_cls = 0.f, s_noobj = 0.f, s_reg = 0.f, s_cont = 0.f;

    const int c = block0 + tid;
    if (c < ncell) {
        bool m;
        if (mode == 0)      m = ((const int*)maskv)[c] != 0;
        else if (mode == 1) m = ((const unsigned char*)maskv)[c] != 0;
        else                m = ((const float*)maskv)[c] != 0.0f;

        const float2* myp = (const float2*)(sp + tid * 30);

        if (!m) {
            // only the two confidences (indices 4 and 9)
            float c0 = myp[2].x;   // float idx 4
            float c1 = myp[4].y;   // float idx 9
            s_noobj = c0 * c0 + c1 * c1;
        } else {
            float pv[30];
#pragma unroll
            for (int j = 0; j < 15; j++) {
                float2 v = myp[j];
                pv[2 * j]     = v.x;
                pv[2 * j + 1] = v.y;
            }

            // ---- class loss ----
            {
                const float4* myt = (const float4*)(st + tid * 20);
                float cls = 0.f;
#pragma unroll
                for (int j = 0; j < 5; j++) {
                    float4 t = myt[j];
                    float d0 = t.x - pv[10 + 4 * j + 0];
                    float d1 = t.y - pv[10 + 4 * j + 1];
                    float d2 = t.z - pv[10 + 4 * j + 2];
                    float d3 = t.w - pv[10 + 4 * j + 3];
                    cls += d0 * d0 + d1 * d1 + d2 * d2 + d3 * d3;
                }
                s_cls = cls;
            }

            // ---- IoU of the two pred boxes vs target ----
            float4 tb = ((const float4*)tbox)[c];
            float t_cx = tb.x * S_GRID_INV;
            float t_cy = tb.y * S_GRID_INV;
            float t_x1 = t_cx - 0.5f * tb.z;
            float t_y1 = t_cy - 0.5f * tb.w;
            float t_x2 = t_cx + 0.5f * tb.z;
            float t_y2 = t_cy + 0.5f * tb.w;
            float area_t = (t_x2 - t_x1) * (t_y2 - t_y1);

            float iou[2];
#pragma unroll
            for (int b = 0; b < 2; b++) {
                float px = pv[5 * b + 0] * S_GRID_INV;
                float py = pv[5 * b + 1] * S_GRID_INV;
                float pw = pv[5 * b + 2];
                float ph = pv[5 * b + 3];
                float p_x1 = px - 0.5f * pw;
                float p_y1 = py - 0.5f * ph;
                float p_x2 = px + 0.5f * pw;
                float p_y2 = py + 0.5f * ph;
                float lt_x = fmaxf(t_x1, p_x1);
                float lt_y = fmaxf(t_y1, p_y1);
                float rb_x = fminf(t_x2, p_x2);
                float rb_y = fminf(t_y2, p_y2);
                float w = fmaxf(rb_x - lt_x, 0.0f);
                float h = fmaxf(rb_y - lt_y, 0.0f);
                float inter = w * h;
                float area_p = (p_x2 - p_x1) * (p_y2 - p_y1);
                iou[b] = inter / (area_t + area_p - inter);
            }

            // argmax (first max wins on tie)
            bool sel = iou[1] > iou[0];
            float best_iou = sel ? iou[1] : iou[0];
            float bb_x = sel ? pv[5] : pv[0];
            float bb_y = sel ? pv[6] : pv[1];
            float bb_w = sel ? pv[7] : pv[2];
            float bb_h = sel ? pv[8] : pv[3];
            float bb_c = sel ? pv[9] : pv[4];

            float dx = bb_x - tb.x;
            float dy = bb_y - tb.y;
            float sw = sqrtf(bb_w) - sqrtf(tb.z);
            float sh = sqrtf(bb_h) - sqrtf(tb.w);
            s_reg = dx * dx + dy * dy + sw * sw + sh * sh;

            float dc = best_iou - bb_c;
            s_cont = dc * dc;
        }
    }

    // ---- block reduction ----
#pragma unroll
    for (int off = 16; off; off >>= 1) {
        s_cls   += __shfl_down_sync(0xFFFFFFFFu, s_cls,   off);
        s_noobj += __shfl_down_sync(0xFFFFFFFFu, s_noobj, off);
        s_reg   += __shfl_down_sync(0xFFFFFFFFu, s_reg,   off);
        s_cont  += __shfl_down_sync(0xFFFFFFFFu, s_cont,  off);
    }

    __shared__ float sm[4][8];
    int wid = tid >> 5;
    int lid = tid & 31;
    if (lid == 0) {
        sm[0][wid] = s_cls;
        sm[1][wid] = s_noobj;
        sm[2][wid] = s_reg;
        sm[3][wid] = s_cont;
    }
    __syncthreads();
    if (tid == 0) {
        float a0 = 0.f, a1 = 0.f, a2 = 0.f, a3 = 0.f;
#pragma unroll
        for (int w = 0; w < 8; w++) {
            a0 += sm[0][w];
            a1 += sm[1][w];
            a2 += sm[2][w];
            a3 += sm[3][w];
        }
        atomicAdd(&g_acc[0], (double)a0);
        atomicAdd(&g_acc[1], (double)a1);
        atomicAdd(&g_acc[2], (double)a2);
        atomicAdd(&g_acc[3], (double)a3);
    }
}

__global__ void finalize_kernel(float* out, int n_batch) {
    double cls   = g_acc[0];
    double noobj = (double)L_NOOBJ * g_acc[1];
    double reg   = (double)L_COORD * g_acc[2];
    double cont  = g_acc[3];
    double total = (cls + noobj + reg + cont) / (double)n_batch;
    out[0] = (float)total;
    out[1] = (float)reg;
    out[2] = (float)cont;
    out[3] = (float)noobj;
    out[4] = (float)cls;
}

extern "C" void kernel_launch(void* const* d_in, const int* in_sizes, int n_in,
                              void* d_out, int out_size) {
    // Identify inputs by element count: pred = 30n, tcls = 20n, tbox = 4n, mask = n
    const void* ptrs[4] = {d_in[0], d_in[1], d_in[2], d_in[3]};
    long long sz[4] = {in_sizes[0], in_sizes[1], in_sizes[2], in_sizes[3]};

    int im = 0;
    for (int i = 1; i < 4; i++) if (sz[i] < sz[im]) im = i;
    long long n = sz[im];

    const float* pred = nullptr;
    const float* tbox = nullptr;
    const float* tcls = nullptr;
    const void*  hmask = ptrs[im];
    for (int i = 0; i < 4; i++) {
        if (i == im) continue;
        if (sz[i] == 30 * n) pred = (const float*)ptrs[i];
        else if (sz[i] == 20 * n) tcls = (const float*)ptrs[i];
        else if (sz[i] == 4 * n) tbox = (const float*)ptrs[i];
    }

    int ncell = (int)n;                 // 802816
    int n_batch = ncell / (14 * 14);    // 4096

    init_acc_kernel<<<1, 32>>>();
    int blocks = (ncell + TPB - 1) / TPB;  // 3136
    yolo_main_kernel<<<blocks, TPB>>>(pred, tbox, tcls, hmask, ncell);
    finalize_kernel<<<1, 1>>>((float*)d_out, n_batch);
}